// round 3
// baseline (speedup 1.0000x reference)
#include <cuda_runtime.h>
#include <math_constants.h>
#include <cstdint>

#define S_LEN 2048
#define D_HEAD 64
#define N_BH 32
#define TQ 64
#define TK 64
#define NTHR 256
#define NEGC (-1000000000.0f)
#define OUT_ELEMS 4194304           /* B*H*S*D */
#define PSTR 65                     /* padded smem row stride (floats) */
#define SM_TILE (TK * PSTR)         /* 4160 floats */

// per-row softmax stats scratch (allowed: __device__ globals)
__device__ float g_m[N_BH * S_LEN];
__device__ float g_l[N_BH * S_LEN];

// ---------------------------------------------------------------------------
// JAX partitionable threefry random bits for element with flat index i
// (n < 2^32 so the 64-bit counter is (hi=0, lo=i)):
//   (o0, o1) = threefry2x32(key=(0,42), (0, i));  bits = o0 ^ o1
// ---------------------------------------------------------------------------
__device__ __forceinline__ uint32_t tf_bits_partitionable(uint32_t i) {
  const uint32_t k0 = 0u, k1 = 42u;
  const uint32_t k2 = 0x1BD11BDAu ^ k0 ^ k1;
  uint32_t x0 = 0u + k0;       // c0 = hi = 0
  uint32_t x1 = i + k1;        // c1 = lo = i
#define TF_MIX(R) { x0 += x1; x1 = __funnelshift_l(x1, x1, (R)); x1 ^= x0; }
  TF_MIX(13) TF_MIX(15) TF_MIX(26) TF_MIX(6)  x0 += k1; x1 += k2 + 1u;
  TF_MIX(17) TF_MIX(29) TF_MIX(16) TF_MIX(24) x0 += k2; x1 += k0 + 2u;
  TF_MIX(13) TF_MIX(15) TF_MIX(26) TF_MIX(6)  x0 += k0; x1 += k1 + 3u;
  TF_MIX(17) TF_MIX(29) TF_MIX(16) TF_MIX(24) x0 += k1; x1 += k2 + 4u;
  TF_MIX(13) TF_MIX(15) TF_MIX(26) TF_MIX(6)  x0 += k2; x1 += k0 + 5u;
#undef TF_MIX
  return x0 ^ x1;
}

// JAX uniform [0,1): mantissa = bits >> 9, OR exponent of 1.0f, minus 1.0f
__device__ __forceinline__ float tf_uniform(uint32_t bits) {
  return __uint_as_float((bits >> 9) | 0x3f800000u) - 1.0f;
}

// ---------------------------------------------------------------------------
// Kernel 1: scores = mask ? (Q K^T)/8 : NEG  -> written raw into p_attn region
//           + online softmax stats (row max m, row sum l) -> g_m/g_l
// grid: (S/TQ, N_BH), 256 threads, 4x4 micro-tile per thread
// ---------------------------------------------------------------------------
__global__ __launch_bounds__(NTHR)
void qk_scores_kernel(const float *__restrict__ Q, const float *__restrict__ K,
                      const int *__restrict__ mask, float *__restrict__ Sc) {
  __shared__ float Qs[TQ * PSTR];
  __shared__ float Ks[TK * PSTR];
  __shared__ int ms[TK];

  const int qt = blockIdx.x, bh = blockIdx.y;
  const int tid = threadIdx.x;
  const int b = bh >> 4;                 // H = 16
  const int ty = tid >> 4, tx = tid & 15;
  const int r0 = ty * 4, c0 = tx * 4;

  const float *Qp = Q + ((size_t)bh * S_LEN + (size_t)qt * TQ) * D_HEAD;
  for (int t = tid; t < TQ * D_HEAD; t += NTHR)
    Qs[(t >> 6) * PSTR + (t & 63)] = Qp[t];

  float m[4], l[4];
#pragma unroll
  for (int i = 0; i < 4; i++) { m[i] = -CUDART_INF_F; l[i] = 0.f; }

#pragma unroll 1
  for (int kt = 0; kt < S_LEN / TK; kt++) {
    __syncthreads();
    const float *Kp = K + ((size_t)bh * S_LEN + (size_t)kt * TK) * D_HEAD;
    for (int t = tid; t < TK * D_HEAD; t += NTHR)
      Ks[(t >> 6) * PSTR + (t & 63)] = Kp[t];
    if (tid < TK) ms[tid] = mask[b * S_LEN + kt * TK + tid];
    __syncthreads();

    float acc[4][4];
#pragma unroll
    for (int i = 0; i < 4; i++)
#pragma unroll
      for (int j = 0; j < 4; j++) acc[i][j] = 0.f;

#pragma unroll 8
    for (int d = 0; d < D_HEAD; d++) {
      float qa[4], ka[4];
#pragma unroll
      for (int i = 0; i < 4; i++) qa[i] = Qs[(r0 + i) * PSTR + d];
#pragma unroll
      for (int j = 0; j < 4; j++) ka[j] = Ks[(c0 + j) * PSTR + d];
#pragma unroll
      for (int i = 0; i < 4; i++)
#pragma unroll
        for (int j = 0; j < 4; j++) acc[i][j] = fmaf(qa[i], ka[j], acc[i][j]);
    }

    float sv[4][4];
#pragma unroll
    for (int j = 0; j < 4; j++) {
      const bool keep = (ms[c0 + j] != 0);
#pragma unroll
      for (int i = 0; i < 4; i++)
        sv[i][j] = keep ? acc[i][j] * 0.125f : NEGC;
    }

#pragma unroll
    for (int i = 0; i < 4; i++) {
      size_t off = ((size_t)bh * S_LEN + (size_t)qt * TQ + r0 + i) * S_LEN +
                   (size_t)kt * TK + c0;
      *reinterpret_cast<float4 *>(Sc + off) =
          make_float4(sv[i][0], sv[i][1], sv[i][2], sv[i][3]);
    }

#pragma unroll
    for (int i = 0; i < 4; i++) {
      float tmax = fmaxf(fmaxf(sv[i][0], sv[i][1]), fmaxf(sv[i][2], sv[i][3]));
#pragma unroll
      for (int o = 8; o; o >>= 1)
        tmax = fmaxf(tmax, __shfl_xor_sync(0xffffffffu, tmax, o));
      const float mnew = fmaxf(m[i], tmax);
      float ts = __expf(sv[i][0] - mnew) + __expf(sv[i][1] - mnew) +
                 __expf(sv[i][2] - mnew) + __expf(sv[i][3] - mnew);
#pragma unroll
      for (int o = 8; o; o >>= 1)
        ts += __shfl_xor_sync(0xffffffffu, ts, o);
      l[i] = l[i] * __expf(m[i] - mnew) + ts;
      m[i] = mnew;
    }
  }

  if (tx == 0) {
#pragma unroll
    for (int i = 0; i < 4; i++) {
      g_m[bh * S_LEN + qt * TQ + r0 + i] = m[i];
      g_l[bh * S_LEN + qt * TQ + r0 + i] = l[i];
    }
  }
}

// ---------------------------------------------------------------------------
// Kernel 2: reads raw scores, applies softmax normalization + JAX
// partitionable-threefry dropout, rewrites p_attn, accumulates out = p @ V.
// grid: (S/TQ, N_BH), 256 threads, static smem
// ---------------------------------------------------------------------------
__global__ __launch_bounds__(NTHR)
void softmax_dropout_pv_kernel(float *__restrict__ P, const float *__restrict__ V,
                               float *__restrict__ O) {
  __shared__ float Vs[SM_TILE];
  __shared__ float Ps[SM_TILE];

  const int qt = blockIdx.x;
  const int bh = blockIdx.y;
  const int tid = threadIdx.x;
  const int ty = tid >> 4, tx = tid & 15;
  const int r0 = ty * 4, c0 = tx * 4;

  float m[4], r[4];
#pragma unroll
  for (int i = 0; i < 4; i++) {
    const int q = qt * TQ + r0 + i;
    m[i] = g_m[bh * S_LEN + q];
    r[i] = 1.0f / g_l[bh * S_LEN + q];
  }

  float o[4][4];
#pragma unroll
  for (int i = 0; i < 4; i++)
#pragma unroll
    for (int j = 0; j < 4; j++) o[i][j] = 0.f;

  const float inv_keep = 1.0f / 0.9f;

#pragma unroll 1
  for (int kt = 0; kt < S_LEN / TK; kt++) {
    __syncthreads();
    const float *Vp = V + ((size_t)bh * S_LEN + (size_t)kt * TK) * D_HEAD;
    for (int t = tid; t < TK * D_HEAD; t += NTHR)
      Vs[(t >> 6) * PSTR + (t & 63)] = Vp[t];

#pragma unroll
    for (int i = 0; i < 4; i++) {
      const size_t idx =
          ((size_t)bh * S_LEN + (size_t)qt * TQ + r0 + i) * S_LEN +
          (size_t)kt * TK + c0;
      const float4 s = *reinterpret_cast<const float4 *>(P + idx);
      float p[4] = {__expf(s.x - m[i]) * r[i], __expf(s.y - m[i]) * r[i],
                    __expf(s.z - m[i]) * r[i], __expf(s.w - m[i]) * r[i]};
#pragma unroll
      for (int j = 0; j < 4; j++) {
        const uint32_t bits = tf_bits_partitionable((uint32_t)idx + (uint32_t)j);
        p[j] = (tf_uniform(bits) < 0.9f) ? p[j] * inv_keep : 0.f;
      }
      *reinterpret_cast<float4 *>(P + idx) =
          make_float4(p[0], p[1], p[2], p[3]);
#pragma unroll
      for (int j = 0; j < 4; j++)
        Ps[(r0 + i) * PSTR + c0 + j] = p[j];
    }
    __syncthreads();

#pragma unroll 4
    for (int c = 0; c < TK; c++) {
      float va[4], pa[4];
#pragma unroll
      for (int j = 0; j < 4; j++) va[j] = Vs[c * PSTR + c0 + j];
#pragma unroll
      for (int i = 0; i < 4; i++) pa[i] = Ps[(r0 + i) * PSTR + c];
#pragma unroll
      for (int i = 0; i < 4; i++)
#pragma unroll
        for (int j = 0; j < 4; j++)
          o[i][j] = fmaf(pa[i], va[j], o[i][j]);
    }
  }

#pragma unroll
  for (int i = 0; i < 4; i++) {
    const size_t off =
        ((size_t)bh * S_LEN + (size_t)qt * TQ + r0 + i) * D_HEAD + c0;
    *reinterpret_cast<float4 *>(O + off) =
        make_float4(o[i][0], o[i][1], o[i][2], o[i][3]);
  }
}

// ---------------------------------------------------------------------------
extern "C" void kernel_launch(void *const *d_in, const int *in_sizes, int n_in,
                              void *d_out, int out_size) {
  const float *Q = (const float *)d_in[0];
  const float *K = (const float *)d_in[1];
  const float *V = (const float *)d_in[2];
  const int *mask = (const int *)d_in[3];
  float *out = (float *)d_out;
  float *P = out + OUT_ELEMS;  // p_attn region of the flattened tuple output

  dim3 g1(S_LEN / TQ, N_BH);
  qk_scores_kernel<<<g1, NTHR>>>(Q, K, mask, P);

  dim3 g2(S_LEN / TQ, N_BH);
  softmax_dropout_pv_kernel<<<g2, NTHR>>>(P, V, out);
}

// round 4
// speedup vs baseline: 1.2452x; 1.2452x over previous
#include <cuda_runtime.h>
#include <cstdint>

#define S_LEN 2048
#define D_HEAD 64
#define N_BH 32
#define NB 2
#define TQ 64
#define TK 64
#define NTHR 256
#define OUT_ELEMS 4194304           /* B*H*S*D */
#define P_ELEMS 134217728           /* B*H*S*S = 2^27 */
#define PSTR 68                     /* padded smem row stride (floats, mult of 4) */
#define NEG30 (-1.0e30f)
#define KEEP_THR 3865470464u        /* bits < THR  <=>  uniform(bits) < 0.9f (exact) */

// ---------------- device scratch (static allocation allowed) ----------------
__device__ float g_m[N_BH * S_LEN];
__device__ float g_l[N_BH * S_LEN];
__device__ __align__(16) int g_colmap[NB][S_LEN];
__device__ int g_cnt[NB];
__device__ __align__(16) float g_sc[(size_t)N_BH * S_LEN * S_LEN]; // compacted scores

// ---------------------------------------------------------------------------
// JAX partitionable threefry bits for flat index i: threefry2x32((0,42),(0,i)),
// folded o0 ^ o1.
// ---------------------------------------------------------------------------
__device__ __forceinline__ uint32_t tf_bits(uint32_t i) {
  const uint32_t k0 = 0u, k1 = 42u;
  const uint32_t k2 = 0x1BD11BDAu ^ k0 ^ k1;
  uint32_t x0 = 0u + k0;
  uint32_t x1 = i + k1;
#define TF_MIX(R) { x0 += x1; x1 = __funnelshift_l(x1, x1, (R)); x1 ^= x0; }
  TF_MIX(13) TF_MIX(15) TF_MIX(26) TF_MIX(6)  x0 += k1; x1 += k2 + 1u;
  TF_MIX(17) TF_MIX(29) TF_MIX(16) TF_MIX(24) x0 += k2; x1 += k0 + 2u;
  TF_MIX(13) TF_MIX(15) TF_MIX(26) TF_MIX(6)  x0 += k0; x1 += k1 + 3u;
  TF_MIX(17) TF_MIX(29) TF_MIX(16) TF_MIX(24) x0 += k1; x1 += k2 + 4u;
  TF_MIX(13) TF_MIX(15) TF_MIX(26) TF_MIX(6)  x0 += k2; x1 += k0 + 5u;
#undef TF_MIX
  return x0 ^ x1;
}

// ---------------------------------------------------------------------------
// Kernel 0: compact unmasked column indices per batch. 1 block of 1024/batch.
// ---------------------------------------------------------------------------
__global__ void compact_mask_kernel(const int *__restrict__ mask) {
  const int b = blockIdx.x;
  const int tid = threadIdx.x;           // 1024 threads
  __shared__ int wpre[32];
  const int i0 = 2 * tid, i1 = 2 * tid + 1;
  const int m0 = (mask[b * S_LEN + i0] != 0);
  const int m1 = (mask[b * S_LEN + i1] != 0);
  const int s = m0 + m1;
  const int lane = tid & 31, w = tid >> 5;
  int x = s;
#pragma unroll
  for (int o = 1; o < 32; o <<= 1) {
    int y = __shfl_up_sync(0xffffffffu, x, o);
    if (lane >= o) x += y;
  }
  if (lane == 31) wpre[w] = x;
  __syncthreads();
  if (w == 0) {
    int v = wpre[lane];
#pragma unroll
    for (int o = 1; o < 32; o <<= 1) {
      int y = __shfl_up_sync(0xffffffffu, v, o);
      if (lane >= o) v += y;
    }
    wpre[lane] = v;
  }
  __syncthreads();
  const int ex = x - s + (w ? wpre[w - 1] : 0);
  const int total = wpre[31];
  g_colmap[b][i0] = 0;                   // padding default
  g_colmap[b][i1] = 0;
  __syncthreads();
  if (m0) g_colmap[b][ex] = i0;
  if (m1) g_colmap[b][ex + m0] = i1;
  if (tid == 0) g_cnt[b] = total;
}

// ---------------------------------------------------------------------------
// Kernel 1: compacted QK^T. Gathers unmasked K rows, writes compacted scaled
// scores to g_sc, computes per-row softmax stats (m, l).
// grid (S/TQ, N_BH), 256 threads, 4x4 micro-tile.
// ---------------------------------------------------------------------------
__global__ __launch_bounds__(NTHR)
void qk_scores_kernel(const float *__restrict__ Q, const float *__restrict__ K) {
  __shared__ float Qs[TQ * PSTR];
  __shared__ float Ks[TK * PSTR];

  const int qt = blockIdx.x, bh = blockIdx.y;
  const int b = bh >> 4;
  const int tid = threadIdx.x;
  const int ty = tid >> 4, tx = tid & 15;
  const int r0 = ty * 4, c0 = tx * 4;
  const int cnt = g_cnt[b];
  const int ntile = (cnt + TK - 1) / TK;
  const int *cmap = g_colmap[b];

  const float *Qp = Q + (size_t)(bh * S_LEN + qt * TQ) * D_HEAD;
  for (int u = tid; u < TQ * (D_HEAD / 4); u += NTHR) {
    const int rr = u >> 4, d4 = (u & 15) * 4;
    *reinterpret_cast<float4 *>(&Qs[rr * PSTR + d4]) =
        *reinterpret_cast<const float4 *>(Qp + rr * D_HEAD + d4);
  }

  float m[4], l[4];
#pragma unroll
  for (int i = 0; i < 4; i++) { m[i] = NEG30; l[i] = 0.f; }

  const float *Kbase = K + (size_t)bh * S_LEN * D_HEAD;

  for (int t = 0; t < ntile; t++) {
    __syncthreads();
    const int jc0 = t * TK;
    for (int u = tid; u < TK * (D_HEAD / 4); u += NTHR) {
      const int rr = u >> 4, d4 = (u & 15) * 4;
      const int col = cmap[jc0 + rr];
      *reinterpret_cast<float4 *>(&Ks[rr * PSTR + d4]) =
          *reinterpret_cast<const float4 *>(Kbase + (size_t)col * D_HEAD + d4);
    }
    __syncthreads();

    float acc[4][4];
#pragma unroll
    for (int i = 0; i < 4; i++)
#pragma unroll
      for (int j = 0; j < 4; j++) acc[i][j] = 0.f;

#pragma unroll
    for (int db = 0; db < D_HEAD / 4; db++) {
      float4 qa[4], ka[4];
#pragma unroll
      for (int i = 0; i < 4; i++)
        qa[i] = *reinterpret_cast<const float4 *>(&Qs[(r0 + i) * PSTR + db * 4]);
#pragma unroll
      for (int j = 0; j < 4; j++)
        ka[j] = *reinterpret_cast<const float4 *>(&Ks[(c0 + j) * PSTR + db * 4]);
#pragma unroll
      for (int i = 0; i < 4; i++)
#pragma unroll
        for (int j = 0; j < 4; j++) {
          acc[i][j] = fmaf(qa[i].x, ka[j].x, acc[i][j]);
          acc[i][j] = fmaf(qa[i].y, ka[j].y, acc[i][j]);
          acc[i][j] = fmaf(qa[i].z, ka[j].z, acc[i][j]);
          acc[i][j] = fmaf(qa[i].w, ka[j].w, acc[i][j]);
        }
    }

    float sv[4][4];
#pragma unroll
    for (int j = 0; j < 4; j++) {
      const bool real = (jc0 + c0 + j) < cnt;
#pragma unroll
      for (int i = 0; i < 4; i++)
        sv[i][j] = real ? acc[i][j] * 0.125f : NEG30;
    }

#pragma unroll
    for (int i = 0; i < 4; i++) {
      const size_t off =
          (size_t)(bh * S_LEN + qt * TQ + r0 + i) * S_LEN + jc0 + c0;
      *reinterpret_cast<float4 *>(&g_sc[off]) =
          make_float4(sv[i][0], sv[i][1], sv[i][2], sv[i][3]);
    }

    // per-thread online m/l (no cross-thread work until the end)
#pragma unroll
    for (int i = 0; i < 4; i++) {
      const float tmax = fmaxf(fmaxf(sv[i][0], sv[i][1]),
                               fmaxf(sv[i][2], sv[i][3]));
      const float mnew = fmaxf(m[i], tmax);
      const float e = __expf(sv[i][0] - mnew) + __expf(sv[i][1] - mnew) +
                      __expf(sv[i][2] - mnew) + __expf(sv[i][3] - mnew);
      l[i] = l[i] * __expf(m[i] - mnew) + e;
      m[i] = mnew;
    }
  }

  // merge (m, l) across the 16 lanes of each row group
#pragma unroll
  for (int o = 8; o; o >>= 1) {
#pragma unroll
    for (int i = 0; i < 4; i++) {
      const float mo = __shfl_xor_sync(0xffffffffu, m[i], o);
      const float lo = __shfl_xor_sync(0xffffffffu, l[i], o);
      const float mn = fmaxf(m[i], mo);
      l[i] = l[i] * __expf(m[i] - mn) + lo * __expf(mo - mn);
      m[i] = mn;
    }
  }
  if (tx == 0) {
#pragma unroll
    for (int i = 0; i < 4; i++) {
      g_m[bh * S_LEN + qt * TQ + r0 + i] = m[i];
      g_l[bh * S_LEN + qt * TQ + r0 + i] = l[i];
    }
  }
}

// ---------------------------------------------------------------------------
// Kernel 2: compacted softmax + dropout + PV. Reads compacted scores, threefry
// only for unmasked elements, scatter-stores kept p into memset-zeroed P,
// gathered-V PV matmul. grid (S/TQ, N_BH), 256 threads.
// ---------------------------------------------------------------------------
__global__ __launch_bounds__(NTHR)
void softmax_dropout_pv_kernel(const float *__restrict__ V,
                               float *__restrict__ P, float *__restrict__ O) {
  __shared__ float Vs[TK * PSTR];
  __shared__ float Ps[TQ * PSTR];

  const int qt = blockIdx.x, bh = blockIdx.y;
  const int b = bh >> 4;
  const int tid = threadIdx.x;
  const int ty = tid >> 4, tx = tid & 15;
  const int r0 = ty * 4, c0 = tx * 4;
  const int cnt = g_cnt[b];
  const int ntile = (cnt + TK - 1) / TK;
  const int *cmap = g_colmap[b];

  float m[4], r2[4];
#pragma unroll
  for (int i = 0; i < 4; i++) {
    const int q = qt * TQ + r0 + i;
    m[i] = g_m[bh * S_LEN + q];
    r2[i] = 1.0f / (g_l[bh * S_LEN + q] * 0.9f);   // fold 1/keep_prob
  }

  float o[4][4];
#pragma unroll
  for (int i = 0; i < 4; i++)
#pragma unroll
    for (int j = 0; j < 4; j++) o[i][j] = 0.f;

  const float *Vbase = V + (size_t)bh * S_LEN * D_HEAD;

  for (int t = 0; t < ntile; t++) {
    __syncthreads();
    const int jc0 = t * TK;
    for (int u = tid; u < TK * (D_HEAD / 4); u += NTHR) {
      const int rr = u >> 4, d4 = (u & 15) * 4;
      const int col = cmap[jc0 + rr];
      *reinterpret_cast<float4 *>(&Vs[rr * PSTR + d4]) =
          *reinterpret_cast<const float4 *>(Vbase + (size_t)col * D_HEAD + d4);
    }

    const int4 cm4 = *reinterpret_cast<const int4 *>(&cmap[jc0 + c0]);
    const int jc = jc0 + c0;

#pragma unroll
    for (int i = 0; i < 4; i++) {
      const uint32_t qrow = (uint32_t)(bh * S_LEN + qt * TQ + r0 + i);
      const size_t srow = (size_t)qrow * S_LEN;
      const float4 s4 = *reinterpret_cast<const float4 *>(&g_sc[srow + jc]);
      const float p0 = __expf(s4.x - m[i]) * r2[i];
      const float p1 = __expf(s4.y - m[i]) * r2[i];
      const float p2 = __expf(s4.z - m[i]) * r2[i];
      const float p3 = __expf(s4.w - m[i]) * r2[i];
      const uint32_t base = qrow * (uint32_t)S_LEN;
      const bool k0 = tf_bits(base + (uint32_t)cm4.x) < KEEP_THR;
      const bool k1 = tf_bits(base + (uint32_t)cm4.y) < KEEP_THR;
      const bool k2b = tf_bits(base + (uint32_t)cm4.z) < KEEP_THR;
      const bool k3 = tf_bits(base + (uint32_t)cm4.w) < KEEP_THR;
      const float pv0 = k0 ? p0 : 0.f;
      const float pv1 = k1 ? p1 : 0.f;
      const float pv2 = k2b ? p2 : 0.f;
      const float pv3 = k3 ? p3 : 0.f;
      *reinterpret_cast<float4 *>(&Ps[(r0 + i) * PSTR + c0]) =
          make_float4(pv0, pv1, pv2, pv3);
      float *Prow = P + srow;
      if (k0 && jc + 0 < cnt) Prow[cm4.x] = pv0;   // dropped/masked stay 0 (memset)
      if (k1 && jc + 1 < cnt) Prow[cm4.y] = pv1;
      if (k2b && jc + 2 < cnt) Prow[cm4.z] = pv2;
      if (k3 && jc + 3 < cnt) Prow[cm4.w] = pv3;
    }
    __syncthreads();

#pragma unroll
    for (int cb = 0; cb < TK / 4; cb++) {
      float4 pa[4], va[4];
#pragma unroll
      for (int i = 0; i < 4; i++)
        pa[i] = *reinterpret_cast<const float4 *>(&Ps[(r0 + i) * PSTR + cb * 4]);
#pragma unroll
      for (int cc = 0; cc < 4; cc++)
        va[cc] = *reinterpret_cast<const float4 *>(&Vs[(cb * 4 + cc) * PSTR + c0]);
#pragma unroll
      for (int i = 0; i < 4; i++) {
        o[i][0] = fmaf(pa[i].x, va[0].x, o[i][0]);
        o[i][1] = fmaf(pa[i].x, va[0].y, o[i][1]);
        o[i][2] = fmaf(pa[i].x, va[0].z, o[i][2]);
        o[i][3] = fmaf(pa[i].x, va[0].w, o[i][3]);
        o[i][0] = fmaf(pa[i].y, va[1].x, o[i][0]);
        o[i][1] = fmaf(pa[i].y, va[1].y, o[i][1]);
        o[i][2] = fmaf(pa[i].y, va[1].z, o[i][2]);
        o[i][3] = fmaf(pa[i].y, va[1].w, o[i][3]);
        o[i][0] = fmaf(pa[i].z, va[2].x, o[i][0]);
        o[i][1] = fmaf(pa[i].z, va[2].y, o[i][1]);
        o[i][2] = fmaf(pa[i].z, va[2].z, o[i][2]);
        o[i][3] = fmaf(pa[i].z, va[2].w, o[i][3]);
        o[i][0] = fmaf(pa[i].w, va[3].x, o[i][0]);
        o[i][1] = fmaf(pa[i].w, va[3].y, o[i][1]);
        o[i][2] = fmaf(pa[i].w, va[3].z, o[i][2]);
        o[i][3] = fmaf(pa[i].w, va[3].w, o[i][3]);
      }
    }
  }

#pragma unroll
  for (int i = 0; i < 4; i++) {
    const size_t off =
        (size_t)(bh * S_LEN + qt * TQ + r0 + i) * D_HEAD + c0;
    *reinterpret_cast<float4 *>(O + off) =
        make_float4(o[i][0], o[i][1], o[i][2], o[i][3]);
  }
}

// ---------------------------------------------------------------------------
extern "C" void kernel_launch(void *const *d_in, const int *in_sizes, int n_in,
                              void *d_out, int out_size) {
  const float *Q = (const float *)d_in[0];
  const float *K = (const float *)d_in[1];
  const float *V = (const float *)d_in[2];
  const int *mask = (const int *)d_in[3];
  float *out = (float *)d_out;
  float *P = out + OUT_ELEMS;  // p_attn region of the flattened tuple output

  cudaMemsetAsync(P, 0, (size_t)P_ELEMS * sizeof(float));

  compact_mask_kernel<<<NB, 1024>>>(mask);

  dim3 g(S_LEN / TQ, N_BH);
  qk_scores_kernel<<<g, NTHR>>>(Q, K);
  softmax_dropout_pv_kernel<<<g, NTHR>>>(V, P, out);
}